// round 17
// baseline (speedup 1.0000x reference)
#include <cuda_runtime.h>
#include <cuda_fp16.h>
#include <math.h>
#include <stdint.h>

#define V 32000
#define H 1024
#define T 32
#define B 64
#define SOS_INDEX 1
#define EOS_INDEX 2
#define GATES (4*H)

#define RSCALE 2048.0f
#define RINV   (1.0f / 2048.0f)

// ---------------------------------------------------------------------------
// Persistent state. EVERY global that receives accesses wider than 4 bytes
// is vector-typed and accessed by vector-unit indexing.
// ---------------------------------------------------------------------------
__device__ float4 g_c_raw[B*H/4];
__device__ uint4  g_xH_raw[B*H/8];
__device__ uint4  g_xL_raw[B*H/8];
__device__ uint4  g_hH_raw[B*H/8];
__device__ uint4  g_hL_raw[B*H/8];
__device__ uint4  g_WihH_raw[GATES*H/8];
__device__ uint4  g_WihL_raw[GATES*H/8];
__device__ uint4  g_WhhH_raw[GATES*H/8];
__device__ uint4  g_WhhL_raw[GATES*H/8];
__device__ uint4  g_WoutH_raw[(size_t)V*H/8];
__device__ uint4  g_WoutL_raw[(size_t)V*H/8];

#define g_c     ((float*)g_c_raw)
#define g_xH    ((__half*)g_xH_raw)
#define g_xL    ((__half*)g_xL_raw)
#define g_hH    ((__half*)g_hH_raw)
#define g_hL    ((__half*)g_hL_raw)

// ---------------------------------------------------------------------------
__device__ __forceinline__ void split_f16(float x, __half& hi, __half& lo) {
    hi = __float2half_rn(x);
    lo = __float2half_rn((x - __half2float(hi)) * RSCALE);
}
__device__ __forceinline__ uint32_t pack2(__half a, __half b) {
    __half2 h = __halves2half2(a, b);
    return *reinterpret_cast<uint32_t*>(&h);
}
__device__ __forceinline__ void mma_f16(float c[4], const uint32_t a[4],
                                        uint32_t b0, uint32_t b1) {
    asm volatile(
        "mma.sync.aligned.m16n8k16.row.col.f32.f16.f16.f32 "
        "{%0,%1,%2,%3}, {%4,%5,%6,%7}, {%8,%9}, {%0,%1,%2,%3};"
        : "+f"(c[0]), "+f"(c[1]), "+f"(c[2]), "+f"(c[3])
        : "r"(a[0]), "r"(a[1]), "r"(a[2]), "r"(a[3]), "r"(b0), "r"(b1));
}
__device__ __forceinline__ void cp16(uint32_t dst_smem, const uint4* src) {
    asm volatile("cp.async.cg.shared.global [%0], [%1], 16;"
                 :: "r"(dst_smem), "l"(src));
}

// ---------------------------------------------------------------------------
// Weight pre-split: one float4 -> one uint2 of hi halves + one of lo halves.
// ---------------------------------------------------------------------------
__global__ __launch_bounds__(256)
void split_weights(const float4* __restrict__ W, uint2* __restrict__ WH,
                   uint2* __restrict__ WL) {
    size_t j = (size_t)blockIdx.x * 256 + threadIdx.x;   // float4 index
    float4 v = W[j];
    __half h0, l0, h1, l1, h2, l2, h3, l3;
    split_f16(v.x, h0, l0); split_f16(v.y, h1, l1);
    split_f16(v.z, h2, l2); split_f16(v.w, h3, l3);
    WH[j] = make_uint2(pack2(h0, h1), pack2(h2, h3));
    WL[j] = make_uint2(pack2(l0, l1), pack2(l2, l3));
}

// ---------------------------------------------------------------------------
__global__ void init_kernel(const float* __restrict__ E,
                            const float* __restrict__ eh,
                            const float* __restrict__ ec) {
    int i = blockIdx.x * blockDim.x + threadIdx.x;   // 0 .. B*H
    int k = i & (H - 1);
    __half hi, lo;
    split_f16(E[SOS_INDEX * H + k], hi, lo);
    g_xH[i] = hi; g_xL[i] = lo;
    split_f16(eh[i], hi, lo);
    g_hH[i] = hi; g_hL[i] = lo;
    g_c[i] = ec[i];
}

#define BKH 64      // halves of K per tile
#define ROWU 9      // uint4 per SMEM row (8 data + 1 skew)
#define ROWH (ROWU*8)

// ---------------------------------------------------------------------------
// Logits GEMM (R16 golden, unchanged): BN=128 -> 250 blocks, single wave.
// ---------------------------------------------------------------------------
template<int KTOT, int BN>
__global__ __launch_bounds__(256)
void logits_gemm(const uint4* __restrict__ BaH, const uint4* __restrict__ BaL,
                 const float* __restrict__ bias1, float* __restrict__ out, int ldc) {
    constexpr int NF  = BN / 16;
    constexpr int BR  = BN / 32;
    constexpr int STG = (128 + 2 * BN) * ROWU;
    constexpr int NT  = KTOT / BKH;
    extern __shared__ uint4 smem[];

    const int n0blk = blockIdx.x * BN;
    const int tid   = threadIdx.x;
    const int warp  = tid >> 5;
    const int lane  = tid & 31;
    const int gid   = lane >> 2;
    const int tig   = lane & 3;

    const int m0  = (warp >> 1) * 16;
    const int n0w = (warp & 1) * (BN / 2);

    const int lm  = tid >> 3;
    const int lv  = tid & 7;

    auto issue_tile = [&](int k0, int stage) {
        uint4* sb = smem + (size_t)stage * STG;
        const int kv = (k0 >> 3) + lv;
        #pragma unroll
        for (int r = 0; r < 2; r++) {
            int m = lm + r * 32;
            uint32_t dH = (uint32_t)__cvta_generic_to_shared(sb + m * ROWU + lv);
            uint32_t dL = (uint32_t)__cvta_generic_to_shared(sb + (64 + m) * ROWU + lv);
            cp16(dH, g_hH_raw + m * (H / 8) + kv);
            cp16(dL, g_hL_raw + m * (H / 8) + kv);
        }
        #pragma unroll
        for (int r = 0; r < BR; r++) {
            int nloc = lm + r * 32;
            size_t n = (size_t)n0blk + nloc;
            uint32_t dH = (uint32_t)__cvta_generic_to_shared(sb + (128 + nloc) * ROWU + lv);
            uint32_t dL = (uint32_t)__cvta_generic_to_shared(sb + (128 + BN + nloc) * ROWU + lv);
            cp16(dH, BaH + n * (KTOT / 8) + kv);
            cp16(dL, BaL + n * (KTOT / 8) + kv);
        }
        asm volatile("cp.async.commit_group;" ::: "memory");
    };

    float c1[NF][4], c2[NF][4];
    #pragma unroll
    for (int nf = 0; nf < NF; nf++)
        #pragma unroll
        for (int j = 0; j < 4; j++) { c1[nf][j] = 0.f; c2[nf][j] = 0.f; }

    issue_tile(0, 0);

    #pragma unroll 1
    for (int kt = 0; kt < NT; kt++) {
        if (kt + 1 < NT) {
            issue_tile((kt + 1) * BKH, (kt + 1) & 1);
            asm volatile("cp.async.wait_group 1;" ::: "memory");
        } else {
            asm volatile("cp.async.wait_group 0;" ::: "memory");
        }
        __syncthreads();

        const __half* base = (const __half*)(smem + (size_t)(kt & 1) * STG);
        const __half* AsH = base;
        const __half* AsL = base + 64 * ROWH;
        const __half* BsH = base + 128 * ROWH;
        const __half* BsL = base + (128 + BN) * ROWH;

        #pragma unroll
        for (int ks = 0; ks < BKH / 16; ks++) {
            const int kb = ks * 16;
            const int ra = (m0 + gid) * ROWH, rb = (m0 + gid + 8) * ROWH;
            uint32_t ah[4], al[4];
            ah[0] = *reinterpret_cast<const uint32_t*>(AsH + ra + kb + 2 * tig);
            ah[1] = *reinterpret_cast<const uint32_t*>(AsH + rb + kb + 2 * tig);
            ah[2] = *reinterpret_cast<const uint32_t*>(AsH + ra + kb + 8 + 2 * tig);
            ah[3] = *reinterpret_cast<const uint32_t*>(AsH + rb + kb + 8 + 2 * tig);
            al[0] = *reinterpret_cast<const uint32_t*>(AsL + ra + kb + 2 * tig);
            al[1] = *reinterpret_cast<const uint32_t*>(AsL + rb + kb + 2 * tig);
            al[2] = *reinterpret_cast<const uint32_t*>(AsL + ra + kb + 8 + 2 * tig);
            al[3] = *reinterpret_cast<const uint32_t*>(AsL + rb + kb + 8 + 2 * tig);

            uint32_t bh[NF][2];
            #pragma unroll
            for (int nf = 0; nf < NF; nf++) {
                int n = (n0w + nf * 8 + gid) * ROWH;
                bh[nf][0] = *reinterpret_cast<const uint32_t*>(BsH + n + kb + 2 * tig);
                bh[nf][1] = *reinterpret_cast<const uint32_t*>(BsH + n + kb + 8 + 2 * tig);
            }
            #pragma unroll
            for (int nf = 0; nf < NF; nf++) mma_f16(c2[nf], al, bh[nf][0], bh[nf][1]);
            #pragma unroll
            for (int nf = 0; nf < NF; nf++) mma_f16(c1[nf], ah, bh[nf][0], bh[nf][1]);
            #pragma unroll
            for (int nf = 0; nf < NF; nf++) {
                int n = (n0w + nf * 8 + gid) * ROWH;
                uint32_t bl0 = *reinterpret_cast<const uint32_t*>(BsL + n + kb + 2 * tig);
                uint32_t bl1 = *reinterpret_cast<const uint32_t*>(BsL + n + kb + 8 + 2 * tig);
                mma_f16(c2[nf], ah, bl0, bl1);
            }
        }
        __syncthreads();
    }

    const int mr0 = m0 + gid;
    const int mr1 = m0 + gid + 8;
    #pragma unroll
    for (int nf = 0; nf < NF; nf++) {
        int nn = n0blk + n0w + nf * 8 + tig * 2;
        float b0 = bias1[nn];
        float b1 = bias1[nn + 1];
        out[(size_t)mr0 * ldc + nn]     = c1[nf][0] + c2[nf][0] * RINV + b0;
        out[(size_t)mr0 * ldc + nn + 1] = c1[nf][1] + c2[nf][1] * RINV + b1;
        out[(size_t)mr1 * ldc + nn]     = c1[nf][2] + c2[nf][2] * RINV + b0;
        out[(size_t)mr1 * ldc + nn + 1] = c1[nf][3] + c2[nf][3] * RINV + b1;
    }
}

// ---------------------------------------------------------------------------
// FUSED gates GEMM + LSTM cell. NOW 3-stage cp.async pipeline (2 tiles
// always in flight) — this kernel runs ~1 CTA/SM (grid 128) and was
// latency-exposed with 2 stages. Compute path unchanged.
// ---------------------------------------------------------------------------
__global__ __launch_bounds__(256)
void gates_cell_gemm(const uint4* __restrict__ WihH, const uint4* __restrict__ WihL,
                     const uint4* __restrict__ WhhH, const uint4* __restrict__ WhhL,
                     const float* __restrict__ bih, const float* __restrict__ bhh) {
    constexpr int BN  = 32;
    constexpr int NF  = 2;
    constexpr int STG = (128 + 2 * BN) * ROWU;
    constexpr int KTOT = 2 * H;
    constexpr int NT  = KTOT / BKH;
    extern __shared__ uint4 smem[];

    const int J0  = blockIdx.x * 8;        // j-range of this block
    const int tid = threadIdx.x;
    const int warp = tid >> 5;
    const int lane = tid & 31;
    const int gid  = lane >> 2;
    const int tig  = lane & 3;

    const int m0  = (warp >> 1) * 16;
    const int n0w = (warp & 1) * (BN / 2);

    const int lm  = tid >> 3;
    const int lv  = tid & 7;

    auto grow_of = [&](int nloc) { return (nloc >> 3) * H + J0 + (nloc & 7); };

    auto issue_tile = [&](int k0, int stage) {
        uint4* sb = smem + (size_t)stage * STG;
        const int kv = (k0 >> 3) + lv;
        #pragma unroll
        for (int r = 0; r < 2; r++) {
            int m = lm + r * 32;
            uint32_t dH = (uint32_t)__cvta_generic_to_shared(sb + m * ROWU + lv);
            uint32_t dL = (uint32_t)__cvta_generic_to_shared(sb + (64 + m) * ROWU + lv);
            if (kv < H / 8) {
                cp16(dH, g_xH_raw + m * (H / 8) + kv);
                cp16(dL, g_xL_raw + m * (H / 8) + kv);
            } else {
                cp16(dH, g_hH_raw + m * (H / 8) + kv - H / 8);
                cp16(dL, g_hL_raw + m * (H / 8) + kv - H / 8);
            }
        }
        {
            int nloc = lm;                  // BR = 1 for BN=32
            size_t n = (size_t)grow_of(nloc);
            uint32_t dH = (uint32_t)__cvta_generic_to_shared(sb + (128 + nloc) * ROWU + lv);
            uint32_t dL = (uint32_t)__cvta_generic_to_shared(sb + (128 + BN + nloc) * ROWU + lv);
            if (kv < H / 8) {
                cp16(dH, WihH + n * (H / 8) + kv);
                cp16(dL, WihL + n * (H / 8) + kv);
            } else {
                cp16(dH, WhhH + n * (H / 8) + kv - H / 8);
                cp16(dL, WhhL + n * (H / 8) + kv - H / 8);
            }
        }
        asm volatile("cp.async.commit_group;" ::: "memory");
    };

    float c1[NF][4], c2[NF][4];
    #pragma unroll
    for (int nf = 0; nf < NF; nf++)
        #pragma unroll
        for (int j = 0; j < 4; j++) { c1[nf][j] = 0.f; c2[nf][j] = 0.f; }

    issue_tile(0, 0);
    issue_tile(BKH, 1);

    #pragma unroll 1
    for (int kt = 0; kt < NT; kt++) {
        if (kt + 2 < NT) {
            issue_tile((kt + 2) * BKH, (kt + 2) % 3);
            asm volatile("cp.async.wait_group 2;" ::: "memory");
        } else if (kt + 1 < NT) {
            asm volatile("cp.async.wait_group 1;" ::: "memory");
        } else {
            asm volatile("cp.async.wait_group 0;" ::: "memory");
        }
        __syncthreads();

        const __half* base = (const __half*)(smem + (size_t)(kt % 3) * STG);
        const __half* AsH = base;
        const __half* AsL = base + 64 * ROWH;
        const __half* BsH = base + 128 * ROWH;
        const __half* BsL = base + (128 + BN) * ROWH;

        #pragma unroll
        for (int ks = 0; ks < BKH / 16; ks++) {
            const int kb = ks * 16;
            const int ra = (m0 + gid) * ROWH, rb = (m0 + gid + 8) * ROWH;
            uint32_t ah[4], al[4];
            ah[0] = *reinterpret_cast<const uint32_t*>(AsH + ra + kb + 2 * tig);
            ah[1] = *reinterpret_cast<const uint32_t*>(AsH + rb + kb + 2 * tig);
            ah[2] = *reinterpret_cast<const uint32_t*>(AsH + ra + kb + 8 + 2 * tig);
            ah[3] = *reinterpret_cast<const uint32_t*>(AsH + rb + kb + 8 + 2 * tig);
            al[0] = *reinterpret_cast<const uint32_t*>(AsL + ra + kb + 2 * tig);
            al[1] = *reinterpret_cast<const uint32_t*>(AsL + rb + kb + 2 * tig);
            al[2] = *reinterpret_cast<const uint32_t*>(AsL + ra + kb + 8 + 2 * tig);
            al[3] = *reinterpret_cast<const uint32_t*>(AsL + rb + kb + 8 + 2 * tig);

            uint32_t bh[NF][2];
            #pragma unroll
            for (int nf = 0; nf < NF; nf++) {
                int n = (n0w + nf * 8 + gid) * ROWH;
                bh[nf][0] = *reinterpret_cast<const uint32_t*>(BsH + n + kb + 2 * tig);
                bh[nf][1] = *reinterpret_cast<const uint32_t*>(BsH + n + kb + 8 + 2 * tig);
            }
            #pragma unroll
            for (int nf = 0; nf < NF; nf++) mma_f16(c2[nf], al, bh[nf][0], bh[nf][1]);
            #pragma unroll
            for (int nf = 0; nf < NF; nf++) mma_f16(c1[nf], ah, bh[nf][0], bh[nf][1]);
            #pragma unroll
            for (int nf = 0; nf < NF; nf++) {
                int n = (n0w + nf * 8 + gid) * ROWH;
                uint32_t bl0 = *reinterpret_cast<const uint32_t*>(BsL + n + kb + 2 * tig);
                uint32_t bl1 = *reinterpret_cast<const uint32_t*>(BsL + n + kb + 8 + 2 * tig);
                mma_f16(c2[nf], ah, bl0, bl1);
            }
        }
        __syncthreads();
    }

    // ---- epilogue: spill gate tile (64 x 32) to SMEM, then fused cell ----
    float* sg = (float*)smem;
    const int mr0 = m0 + gid;
    const int mr1 = m0 + gid + 8;
    #pragma unroll
    for (int nf = 0; nf < NF; nf++) {
        int nloc = n0w + nf * 8 + tig * 2;
        int gr0 = grow_of(nloc), gr1 = grow_of(nloc + 1);
        float b0 = bih[gr0] + bhh[gr0];
        float b1 = bih[gr1] + bhh[gr1];
        sg[mr0 * 32 + nloc]     = c1[nf][0] + c2[nf][0] * RINV + b0;
        sg[mr0 * 32 + nloc + 1] = c1[nf][1] + c2[nf][1] * RINV + b1;
        sg[mr1 * 32 + nloc]     = c1[nf][2] + c2[nf][2] * RINV + b0;
        sg[mr1 * 32 + nloc + 1] = c1[nf][3] + c2[nf][3] * RINV + b1;
    }
    __syncthreads();

    #pragma unroll
    for (int e = tid; e < 512; e += 256) {
        int b = e >> 3, r = e & 7;
        float ig = sg[b * 32 + r];
        float fg = sg[b * 32 + 8 + r];
        float gg = sg[b * 32 + 16 + r];
        float og = sg[b * 32 + 24 + r];
        int idx = b * H + J0 + r;
        float c  = g_c[idx];
        float si = 1.f / (1.f + expf(-ig));
        float sf = 1.f / (1.f + expf(-fg));
        float so = 1.f / (1.f + expf(-og));
        float cn = sf * c + si * tanhf(gg);
        float hn = so * tanhf(cn);
        g_c[idx] = cn;
        __half hi, lo;
        split_f16(hn, hi, lo);
        g_hH[idx] = hi; g_hL[idx] = lo;
    }
}

// ---------------------------------------------------------------------------
// ONLINE single-pass softmax + argmax + greedy feedback.
// Running (max, argmax, rescaled expsum) per thread, then associative merge
// (greater value wins; on equal value, lower index wins — matches
// jnp.argmax first-index semantics exactly).
// ---------------------------------------------------------------------------
__device__ __forceinline__ void sm_merge(float& m, int& ix, float& s,
                                         float om, int oi, float os) {
    if (om > m || (om == m && oi < ix)) {
        s = os + ((m == -INFINITY) ? 0.f : s * expf(m - om));
        m = om; ix = oi;
    } else {
        s = s + ((om == -INFINITY) ? 0.f : os * expf(om - m));
    }
}

__global__ __launch_bounds__(1024)
void softmax_argmax(const float* __restrict__ logits, const float* __restrict__ E,
                    float* __restrict__ mask_out) {
    const int b    = blockIdx.x;
    const int tid  = threadIdx.x;
    const int lane = tid & 31;
    const int wrp  = tid >> 5;
    const float4* row4 = reinterpret_cast<const float4*>(logits + (size_t)b * V);

    float m = -INFINITY; int ix = 0x7fffffff; float s = 0.f;
    for (int q = tid; q < V / 4; q += 1024) {
        float4 x = row4[q];
        int v = q * 4;
        // ascending index order; strict > keeps lowest index on ties
        if (x.x > m) { s = s * expf(m - x.x) + 1.f; m = x.x; ix = v; }
        else         { s += expf(x.x - m); }
        if (x.y > m) { s = s * expf(m - x.y) + 1.f; m = x.y; ix = v + 1; }
        else         { s += expf(x.y - m); }
        if (x.z > m) { s = s * expf(m - x.z) + 1.f; m = x.z; ix = v + 2; }
        else         { s += expf(x.z - m); }
        if (x.w > m) { s = s * expf(m - x.w) + 1.f; m = x.w; ix = v + 3; }
        else         { s += expf(x.w - m); }
    }
    // note: first update has m=-INFINITY -> expf(-inf)=0 -> s=1 (correct)

    #pragma unroll
    for (int d = 16; d > 0; d >>= 1) {
        float om = __shfl_down_sync(0xffffffffu, m, d);
        int   oi = __shfl_down_sync(0xffffffffu, ix, d);
        float os = __shfl_down_sync(0xffffffffu, s, d);
        sm_merge(m, ix, s, om, oi, os);
    }
    __shared__ float wm[32]; __shared__ int wi[32]; __shared__ float ws[32];
    if (lane == 0) { wm[wrp] = m; wi[wrp] = ix; ws[wrp] = s; }
    __syncthreads();
    __shared__ float s_gmax, s_gsum;
    __shared__ int   s_amax;
    if (wrp == 0) {
        float M = wm[lane]; int I = wi[lane]; float S = ws[lane];
        #pragma unroll
        for (int d = 16; d > 0; d >>= 1) {
            float om = __shfl_down_sync(0xffffffffu, M, d);
            int   oi = __shfl_down_sync(0xffffffffu, I, d);
            float os = __shfl_down_sync(0xffffffffu, S, d);
            sm_merge(M, I, S, om, oi, os);
        }
        if (lane == 0) { s_gmax = M; s_amax = I; s_gsum = S; }
    }
    __syncthreads();
    if (tid == 0)
        mask_out[b] = expf(logits[(size_t)b * V + EOS_INDEX] - s_gmax) / s_gsum;

    // greedy feedback: x_next = E[argmax], stored pre-split (scalar 2B)
    const int amax = s_amax;
    __half hi, lo;
    split_f16(E[(size_t)amax * H + tid], hi, lo);
    g_xH[b * H + tid] = hi;
    g_xL[b * H + tid] = lo;
}

// ---------------------------------------------------------------------------
extern "C" void kernel_launch(void* const* d_in, const int* in_sizes, int n_in,
                              void* d_out, int out_size) {
    const float* E    = (const float*)d_in[0];
    const float* Wih  = (const float*)d_in[1];
    const float* Whh  = (const float*)d_in[2];
    const float* bih  = (const float*)d_in[3];
    const float* bhh  = (const float*)d_in[4];
    const float* Wout = (const float*)d_in[5];
    const float* bout = (const float*)d_in[6];
    const float* eh   = (const float*)d_in[7];
    const float* ec   = (const float*)d_in[8];

    float* out   = (float*)d_out;                       // [T][B][V] logits
    float* masks = out + (size_t)T * B * V;             // [T][B]

    // Resolve DEVICE addresses of all symbols passed as kernel args.
    void *pWihH, *pWihL, *pWhhH, *pWhhL, *pWoutH, *pWoutL;
    cudaGetSymbolAddress(&pWihH, g_WihH_raw);
    cudaGetSymbolAddress(&pWihL, g_WihL_raw);
    cudaGetSymbolAddress(&pWhhH, g_WhhH_raw);
    cudaGetSymbolAddress(&pWhhL, g_WhhL_raw);
    cudaGetSymbolAddress(&pWoutH, g_WoutH_raw);
    cudaGetSymbolAddress(&pWoutL, g_WoutL_raw);

    // Dynamic SMEM sizes. Gates: 3 stages; logits: 2 stages.
    const int smem_gates  = (128 + 2 * 32) * ROWU * 16 * 3;    // 82944 B
    const int smem_logits = (128 + 2 * 128) * ROWU * 16 * 2;   // 110592 B
    cudaFuncSetAttribute(gates_cell_gemm,
                         cudaFuncAttributeMaxDynamicSharedMemorySize, smem_gates);
    cudaFuncSetAttribute(logits_gemm<H, 128>,
                         cudaFuncAttributeMaxDynamicSharedMemorySize, smem_logits);

    // One-time (per launch) weight pre-split. grid = elems/4/256.
    split_weights<<<GATES * H / 1024, 256>>>(
        (const float4*)Wih, (uint2*)pWihH, (uint2*)pWihL);
    split_weights<<<GATES * H / 1024, 256>>>(
        (const float4*)Whh, (uint2*)pWhhH, (uint2*)pWhhL);
    split_weights<<<(int)((size_t)V * H / 1024), 256>>>(
        (const float4*)Wout, (uint2*)pWoutH, (uint2*)pWoutL);

    init_kernel<<<(B * H) / 256, 256>>>(E, eh, ec);
    for (int t = 0; t < T; t++) {
        float* lg = out + (size_t)t * B * V;
        // fused gates GEMM + cell: 128 blocks (8 j-values each), 3-stage pipe
        gates_cell_gemm<<<H / 8, 256, smem_gates>>>(
            (const uint4*)pWihH, (const uint4*)pWihL,
            (const uint4*)pWhhH, (const uint4*)pWhhL, bih, bhh);
        // logits: [64 x 32000] = h * Wout^T, BN=128 -> 250 blocks (1 wave)
        logits_gemm<H, 128><<<V / 128, 256, smem_logits>>>(
            (const uint4*)pWoutH, (const uint4*)pWoutL, bout, lg, V);
        softmax_argmax<<<B, 1024>>>(lg, E, masks + t * B);
    }
}